// round 1
// baseline (speedup 1.0000x reference)
#include <cuda_runtime.h>

// Problem constants (fixed shapes for this problem instance)
#define WSZ   64          // window size
#define NC    48          // channels
#define NT    3           // T summation terms
#define NB    4           // batch
#define IMG   512         // H = W = 512
#define KTOT  (NT*NC)     // 144 combined (t,c) reduction for stage 3
#define NWIN  (NB*8*8)    // 256 windows
#define WIN_SLAB (KTOT*WSZ*WSZ)   // 589824 floats per window in scratch

// Scratch: G[win][(t*48+c)][H'*64+W']  -> 256 * 144 * 4096 floats = 576 MiB
__device__ __align__(16) float g_tmp[(size_t)NWIN * WIN_SLAB];

// ---------------------------------------------------------------------------
// Kernel A: per (b, c, p, q) window-channel slice, compute for each t:
//   tmp1[h][W'] = sum_w X[h][w]   * Ws[t][w][W']
//   tmp2[H'][W'] = sum_h Hs[t][h][H'] * tmp1[h][W']
// and store tmp2 into g_tmp[win][(t*NC+c)][H'*64+W'].
// 256 threads, 16x16 thread grid, 4x4 register tile, outer-product GEMMs.
// ---------------------------------------------------------------------------
__global__ __launch_bounds__(256) void k_stage12(
    const float* __restrict__ x,
    const float* __restrict__ Ws,
    const float* __restrict__ Hs)
{
    __shared__ __align__(16) float sX[WSZ*WSZ];   // X[h][w]
    __shared__ __align__(16) float sT[WSZ*WSZ];   // tmp1[h][W']
    __shared__ __align__(16) float sF[WSZ*WSZ];   // factor (Ws_t, then Hs_t)

    const int tid = threadIdx.x;
    const int q = blockIdx.x & 7;
    const int p = blockIdx.x >> 3;
    const int c = blockIdx.y;
    const int b = blockIdx.z;

    // Load the 64x64 input window (coalesced float4)
    const float* xw = x + (((size_t)(b*NC + c)*IMG + (size_t)p*WSZ)*IMG + (size_t)q*WSZ);
    #pragma unroll
    for (int i = 0; i < 4; i++) {
        int idx4 = i*256 + tid;           // float4 index 0..1023
        int h  = idx4 >> 4;               // 16 float4 per row
        int w4 = (idx4 & 15) << 2;
        *(float4*)&sX[h*WSZ + w4] = *(const float4*)&xw[(size_t)h*IMG + w4];
    }

    const int ty = tid >> 4, tx = tid & 15;
    const int r0 = ty * 4;                // output row block (h / H')
    const int c0 = tx * 4;                // output col block (W')
    float* gwin = g_tmp + (size_t)((b*8 + p)*8 + q) * WIN_SLAB;

    for (int t = 0; t < NT; t++) {
        __syncthreads();  // previous iteration's reads of sF/sT complete (and sX ready on t=0)

        // Load Ws_t into sF
        {
            const float4* wsp = (const float4*)(Ws + (size_t)t*WSZ*WSZ);
            float4* dst = (float4*)sF;
            #pragma unroll
            for (int i = 0; i < 4; i++) dst[i*256 + tid] = wsp[i*256 + tid];
        }
        __syncthreads();

        // GEMM1: tmp1 = X * Ws_t
        float acc[4][4];
        #pragma unroll
        for (int i = 0; i < 4; i++)
            #pragma unroll
            for (int j = 0; j < 4; j++) acc[i][j] = 0.0f;

        #pragma unroll 8
        for (int w = 0; w < WSZ; w++) {
            float4 bv = *(const float4*)&sF[w*WSZ + c0];
            float a0 = sX[(r0+0)*WSZ + w];
            float a1 = sX[(r0+1)*WSZ + w];
            float a2 = sX[(r0+2)*WSZ + w];
            float a3 = sX[(r0+3)*WSZ + w];
            acc[0][0] += a0*bv.x; acc[0][1] += a0*bv.y; acc[0][2] += a0*bv.z; acc[0][3] += a0*bv.w;
            acc[1][0] += a1*bv.x; acc[1][1] += a1*bv.y; acc[1][2] += a1*bv.z; acc[1][3] += a1*bv.w;
            acc[2][0] += a2*bv.x; acc[2][1] += a2*bv.y; acc[2][2] += a2*bv.z; acc[2][3] += a2*bv.w;
            acc[3][0] += a3*bv.x; acc[3][1] += a3*bv.y; acc[3][2] += a3*bv.z; acc[3][3] += a3*bv.w;
        }
        #pragma unroll
        for (int i = 0; i < 4; i++)
            *(float4*)&sT[(r0+i)*WSZ + c0] =
                make_float4(acc[i][0], acc[i][1], acc[i][2], acc[i][3]);
        __syncthreads();  // sT complete; all reads of sF (Ws_t) done

        // Load Hs_t into sF
        {
            const float4* hsp = (const float4*)(Hs + (size_t)t*WSZ*WSZ);
            float4* dst = (float4*)sF;
            #pragma unroll
            for (int i = 0; i < 4; i++) dst[i*256 + tid] = hsp[i*256 + tid];
        }
        __syncthreads();

        // GEMM2: tmp2[H'][W'] = sum_h Hs_t[h][H'] * tmp1[h][W']
        #pragma unroll
        for (int i = 0; i < 4; i++)
            #pragma unroll
            for (int j = 0; j < 4; j++) acc[i][j] = 0.0f;

        #pragma unroll 8
        for (int h = 0; h < WSZ; h++) {
            float4 av = *(const float4*)&sF[h*WSZ + r0];  // Hs_t[h][H'=r0..r0+3]
            float4 bv = *(const float4*)&sT[h*WSZ + c0];  // tmp1[h][W'=c0..c0+3]
            acc[0][0] += av.x*bv.x; acc[0][1] += av.x*bv.y; acc[0][2] += av.x*bv.z; acc[0][3] += av.x*bv.w;
            acc[1][0] += av.y*bv.x; acc[1][1] += av.y*bv.y; acc[1][2] += av.y*bv.z; acc[1][3] += av.y*bv.w;
            acc[2][0] += av.z*bv.x; acc[2][1] += av.z*bv.y; acc[2][2] += av.z*bv.z; acc[2][3] += av.z*bv.w;
            acc[3][0] += av.w*bv.x; acc[3][1] += av.w*bv.y; acc[3][2] += av.w*bv.z; acc[3][3] += av.w*bv.w;
        }

        float* go = gwin + (size_t)(t*NC + c) * (WSZ*WSZ);
        #pragma unroll
        for (int i = 0; i < 4; i++)
            *(float4*)&go[(r0+i)*WSZ + c0] =
                make_float4(acc[i][0], acc[i][1], acc[i][2], acc[i][3]);
    }
}

// ---------------------------------------------------------------------------
// Kernel B: per window, out[C'][n] = sum_{k=(t,c)} Cs[k][C'] * G[win][k][n]
// M=48, K=144, N=4096 GEMM. Grid: (N/128 tiles, 256 windows).
// 256 threads = 8 Cgroups x 32 ngroups; thread tile 6(C') x 4(n).
// ---------------------------------------------------------------------------
__global__ __launch_bounds__(256) void k_stage3(
    const float* __restrict__ Cs,
    float* __restrict__ out)
{
    __shared__ __align__(16) float sC[KTOT*NC];     // 144*48 = 6912 floats
    __shared__ __align__(16) float sG[16*128];      // k-chunk of G tile

    const int tid   = threadIdx.x;
    const int win   = blockIdx.y;
    const int ntile = blockIdx.x * 128;

    // Stage Cs (layout already [t][c][C'] = [k][C'])
    {
        const float4* src = (const float4*)Cs;
        float4* dst = (float4*)sC;
        for (int i = tid; i < (KTOT*NC)/4; i += 256) dst[i] = src[i];
    }

    const float* gw = g_tmp + (size_t)win * WIN_SLAB + ntile;
    const int mg = tid >> 5;          // 0..7
    const int ng = tid & 31;          // 0..31
    const int C0 = mg * 6;
    const int n0 = ng * 4;

    float acc[6][4];
    #pragma unroll
    for (int i = 0; i < 6; i++)
        #pragma unroll
        for (int j = 0; j < 4; j++) acc[i][j] = 0.0f;

    for (int k0 = 0; k0 < KTOT; k0 += 16) {
        __syncthreads();  // previous chunk's sG reads done (also covers sC on k0=0)
        // Load 16 rows x 128 cols of G (512 float4, 2 per thread, coalesced)
        #pragma unroll
        for (int i = 0; i < 2; i++) {
            int idx4 = i*256 + tid;            // 0..511
            int kk = idx4 >> 5;                // row (32 float4 per row)
            int j4 = (idx4 & 31) << 2;
            *(float4*)&sG[kk*128 + j4] =
                *(const float4*)&gw[(size_t)(k0 + kk)*(WSZ*WSZ) + j4];
        }
        __syncthreads();

        #pragma unroll
        for (int kk = 0; kk < 16; kk++) {
            float4 gv = *(const float4*)&sG[kk*128 + n0];
            const float* cr = &sC[(k0 + kk)*NC + C0];
            float cv0 = cr[0], cv1 = cr[1], cv2 = cr[2];
            float cv3 = cr[3], cv4 = cr[4], cv5 = cr[5];
            acc[0][0] += cv0*gv.x; acc[0][1] += cv0*gv.y; acc[0][2] += cv0*gv.z; acc[0][3] += cv0*gv.w;
            acc[1][0] += cv1*gv.x; acc[1][1] += cv1*gv.y; acc[1][2] += cv1*gv.z; acc[1][3] += cv1*gv.w;
            acc[2][0] += cv2*gv.x; acc[2][1] += cv2*gv.y; acc[2][2] += cv2*gv.z; acc[2][3] += cv2*gv.w;
            acc[3][0] += cv3*gv.x; acc[3][1] += cv3*gv.y; acc[3][2] += cv3*gv.z; acc[3][3] += cv3*gv.w;
            acc[4][0] += cv4*gv.x; acc[4][1] += cv4*gv.y; acc[4][2] += cv4*gv.z; acc[4][3] += cv4*gv.w;
            acc[5][0] += cv5*gv.x; acc[5][1] += cv5*gv.y; acc[5][2] += cv5*gv.z; acc[5][3] += cv5*gv.w;
        }
    }

    // Scatter to output: out[b][C'][p*64+H'][q*64+W']
    const int b = win >> 6;
    const int p = (win >> 3) & 7;
    const int q = win & 7;
    const int n  = ntile + n0;        // n0 multiple of 4, row of 64 never crossed
    const int Hp = n >> 6;
    const int Wp = n & 63;
    #pragma unroll
    for (int i = 0; i < 6; i++) {
        int Cp = C0 + i;
        float* op = out + ((((size_t)b*NC + Cp)*IMG + (size_t)p*WSZ + Hp)*IMG
                           + (size_t)q*WSZ + Wp);
        *(float4*)op = make_float4(acc[i][0], acc[i][1], acc[i][2], acc[i][3]);
    }
}

extern "C" void kernel_launch(void* const* d_in, const int* in_sizes, int n_in,
                              void* d_out, int out_size)
{
    const float* x  = (const float*)d_in[0];
    const float* Ws = (const float*)d_in[1];
    const float* Hs = (const float*)d_in[2];
    const float* Cs = (const float*)d_in[3];
    float* out = (float*)d_out;

    dim3 gA(64, NC, NB);        // (p*8+q, c, b) -> 12288 CTAs
    k_stage12<<<gA, 256>>>(x, Ws, Hs);

    dim3 gB(WSZ*WSZ/128, NWIN); // (32 n-tiles, 256 windows) -> 8192 CTAs
    k_stage3<<<gB, 256>>>(Cs, out);
}

// round 2
// speedup vs baseline: 1.0006x; 1.0006x over previous
#include <cuda_runtime.h>

// Problem constants (fixed shapes for this problem instance)
#define WSZ   64          // window size
#define NC    48          // channels
#define NT    3           // T summation terms
#define NB    4           // batch
#define IMG   512         // H = W = 512
#define KTOT  (NT*NC)     // 144 combined (t,c) reduction for stage 3
#define NWIN  (NB*8*8)    // 256 windows
#define WIN_SLAB (KTOT*WSZ*WSZ)   // 589824 floats per window in scratch

// Scratch: G[win][(t*48+c)][H'*64+W']  -> 256 * 144 * 4096 floats = 576 MiB
__device__ __align__(16) float g_tmp[(size_t)NWIN * WIN_SLAB];

// ---------------------------------------------------------------------------
// Kernel A: per (b, c, p, q) window-channel slice, compute for each t:
//   tmp1[h][W'] = sum_w X[h][w]   * Ws[t][w][W']
//   tmp2[H'][W'] = sum_h Hs[t][h][H'] * tmp1[h][W']
// and store tmp2 into g_tmp[win][(t*NC+c)][H'*64+W'].
// 256 threads, 16x16 thread grid, 4x4 register tile, outer-product GEMMs.
// ---------------------------------------------------------------------------
__global__ __launch_bounds__(256) void k_stage12(
    const float* __restrict__ x,
    const float* __restrict__ Ws,
    const float* __restrict__ Hs)
{
    __shared__ __align__(16) float sX[WSZ*WSZ];   // X[h][w]
    __shared__ __align__(16) float sT[WSZ*WSZ];   // tmp1[h][W']
    __shared__ __align__(16) float sF[WSZ*WSZ];   // factor (Ws_t, then Hs_t)

    const int tid = threadIdx.x;
    const int q = blockIdx.x & 7;
    const int p = blockIdx.x >> 3;
    const int c = blockIdx.y;
    const int b = blockIdx.z;

    // Load the 64x64 input window (coalesced float4)
    const float* xw = x + (((size_t)(b*NC + c)*IMG + (size_t)p*WSZ)*IMG + (size_t)q*WSZ);
    #pragma unroll
    for (int i = 0; i < 4; i++) {
        int idx4 = i*256 + tid;           // float4 index 0..1023
        int h  = idx4 >> 4;               // 16 float4 per row
        int w4 = (idx4 & 15) << 2;
        *(float4*)&sX[h*WSZ + w4] = *(const float4*)&xw[(size_t)h*IMG + w4];
    }

    const int ty = tid >> 4, tx = tid & 15;
    const int r0 = ty * 4;                // output row block (h / H')
    const int c0 = tx * 4;                // output col block (W')
    float* gwin = g_tmp + (size_t)((b*8 + p)*8 + q) * WIN_SLAB;

    for (int t = 0; t < NT; t++) {
        __syncthreads();  // previous iteration's reads of sF/sT complete (and sX ready on t=0)

        // Load Ws_t into sF
        {
            const float4* wsp = (const float4*)(Ws + (size_t)t*WSZ*WSZ);
            float4* dst = (float4*)sF;
            #pragma unroll
            for (int i = 0; i < 4; i++) dst[i*256 + tid] = wsp[i*256 + tid];
        }
        __syncthreads();

        // GEMM1: tmp1 = X * Ws_t
        float acc[4][4];
        #pragma unroll
        for (int i = 0; i < 4; i++)
            #pragma unroll
            for (int j = 0; j < 4; j++) acc[i][j] = 0.0f;

        #pragma unroll 8
        for (int w = 0; w < WSZ; w++) {
            float4 bv = *(const float4*)&sF[w*WSZ + c0];
            float a0 = sX[(r0+0)*WSZ + w];
            float a1 = sX[(r0+1)*WSZ + w];
            float a2 = sX[(r0+2)*WSZ + w];
            float a3 = sX[(r0+3)*WSZ + w];
            acc[0][0] += a0*bv.x; acc[0][1] += a0*bv.y; acc[0][2] += a0*bv.z; acc[0][3] += a0*bv.w;
            acc[1][0] += a1*bv.x; acc[1][1] += a1*bv.y; acc[1][2] += a1*bv.z; acc[1][3] += a1*bv.w;
            acc[2][0] += a2*bv.x; acc[2][1] += a2*bv.y; acc[2][2] += a2*bv.z; acc[2][3] += a2*bv.w;
            acc[3][0] += a3*bv.x; acc[3][1] += a3*bv.y; acc[3][2] += a3*bv.z; acc[3][3] += a3*bv.w;
        }
        #pragma unroll
        for (int i = 0; i < 4; i++)
            *(float4*)&sT[(r0+i)*WSZ + c0] =
                make_float4(acc[i][0], acc[i][1], acc[i][2], acc[i][3]);
        __syncthreads();  // sT complete; all reads of sF (Ws_t) done

        // Load Hs_t into sF
        {
            const float4* hsp = (const float4*)(Hs + (size_t)t*WSZ*WSZ);
            float4* dst = (float4*)sF;
            #pragma unroll
            for (int i = 0; i < 4; i++) dst[i*256 + tid] = hsp[i*256 + tid];
        }
        __syncthreads();

        // GEMM2: tmp2[H'][W'] = sum_h Hs_t[h][H'] * tmp1[h][W']
        #pragma unroll
        for (int i = 0; i < 4; i++)
            #pragma unroll
            for (int j = 0; j < 4; j++) acc[i][j] = 0.0f;

        #pragma unroll 8
        for (int h = 0; h < WSZ; h++) {
            float4 av = *(const float4*)&sF[h*WSZ + r0];  // Hs_t[h][H'=r0..r0+3]
            float4 bv = *(const float4*)&sT[h*WSZ + c0];  // tmp1[h][W'=c0..c0+3]
            acc[0][0] += av.x*bv.x; acc[0][1] += av.x*bv.y; acc[0][2] += av.x*bv.z; acc[0][3] += av.x*bv.w;
            acc[1][0] += av.y*bv.x; acc[1][1] += av.y*bv.y; acc[1][2] += av.y*bv.z; acc[1][3] += av.y*bv.w;
            acc[2][0] += av.z*bv.x; acc[2][1] += av.z*bv.y; acc[2][2] += av.z*bv.z; acc[2][3] += av.z*bv.w;
            acc[3][0] += av.w*bv.x; acc[3][1] += av.w*bv.y; acc[3][2] += av.w*bv.z; acc[3][3] += av.w*bv.w;
        }

        float* go = gwin + (size_t)(t*NC + c) * (WSZ*WSZ);
        #pragma unroll
        for (int i = 0; i < 4; i++)
            *(float4*)&go[(r0+i)*WSZ + c0] =
                make_float4(acc[i][0], acc[i][1], acc[i][2], acc[i][3]);
    }
}

// ---------------------------------------------------------------------------
// Kernel B: per window, out[C'][n] = sum_{k=(t,c)} Cs[k][C'] * G[win][k][n]
// M=48, K=144, N=4096 GEMM. Grid: (N/128 tiles, 256 windows).
// 256 threads = 8 Cgroups x 32 ngroups; thread tile 6(C') x 4(n).
// ---------------------------------------------------------------------------
__global__ __launch_bounds__(256) void k_stage3(
    const float* __restrict__ Cs,
    float* __restrict__ out)
{
    __shared__ __align__(16) float sC[KTOT*NC];     // 144*48 = 6912 floats
    __shared__ __align__(16) float sG[16*128];      // k-chunk of G tile

    const int tid   = threadIdx.x;
    const int win   = blockIdx.y;
    const int ntile = blockIdx.x * 128;

    // Stage Cs (layout already [t][c][C'] = [k][C'])
    {
        const float4* src = (const float4*)Cs;
        float4* dst = (float4*)sC;
        for (int i = tid; i < (KTOT*NC)/4; i += 256) dst[i] = src[i];
    }

    const float* gw = g_tmp + (size_t)win * WIN_SLAB + ntile;
    const int mg = tid >> 5;          // 0..7
    const int ng = tid & 31;          // 0..31
    const int C0 = mg * 6;
    const int n0 = ng * 4;

    float acc[6][4];
    #pragma unroll
    for (int i = 0; i < 6; i++)
        #pragma unroll
        for (int j = 0; j < 4; j++) acc[i][j] = 0.0f;

    for (int k0 = 0; k0 < KTOT; k0 += 16) {
        __syncthreads();  // previous chunk's sG reads done (also covers sC on k0=0)
        // Load 16 rows x 128 cols of G (512 float4, 2 per thread, coalesced)
        #pragma unroll
        for (int i = 0; i < 2; i++) {
            int idx4 = i*256 + tid;            // 0..511
            int kk = idx4 >> 5;                // row (32 float4 per row)
            int j4 = (idx4 & 31) << 2;
            *(float4*)&sG[kk*128 + j4] =
                *(const float4*)&gw[(size_t)(k0 + kk)*(WSZ*WSZ) + j4];
        }
        __syncthreads();

        #pragma unroll
        for (int kk = 0; kk < 16; kk++) {
            float4 gv = *(const float4*)&sG[kk*128 + n0];
            const float* cr = &sC[(k0 + kk)*NC + C0];
            float cv0 = cr[0], cv1 = cr[1], cv2 = cr[2];
            float cv3 = cr[3], cv4 = cr[4], cv5 = cr[5];
            acc[0][0] += cv0*gv.x; acc[0][1] += cv0*gv.y; acc[0][2] += cv0*gv.z; acc[0][3] += cv0*gv.w;
            acc[1][0] += cv1*gv.x; acc[1][1] += cv1*gv.y; acc[1][2] += cv1*gv.z; acc[1][3] += cv1*gv.w;
            acc[2][0] += cv2*gv.x; acc[2][1] += cv2*gv.y; acc[2][2] += cv2*gv.z; acc[2][3] += cv2*gv.w;
            acc[3][0] += cv3*gv.x; acc[3][1] += cv3*gv.y; acc[3][2] += cv3*gv.z; acc[3][3] += cv3*gv.w;
            acc[4][0] += cv4*gv.x; acc[4][1] += cv4*gv.y; acc[4][2] += cv4*gv.z; acc[4][3] += cv4*gv.w;
            acc[5][0] += cv5*gv.x; acc[5][1] += cv5*gv.y; acc[5][2] += cv5*gv.z; acc[5][3] += cv5*gv.w;
        }
    }

    // Scatter to output: out[b][C'][p*64+H'][q*64+W']
    const int b = win >> 6;
    const int p = (win >> 3) & 7;
    const int q = win & 7;
    const int n  = ntile + n0;        // n0 multiple of 4, row of 64 never crossed
    const int Hp = n >> 6;
    const int Wp = n & 63;
    #pragma unroll
    for (int i = 0; i < 6; i++) {
        int Cp = C0 + i;
        float* op = out + ((((size_t)b*NC + Cp)*IMG + (size_t)p*WSZ + Hp)*IMG
                           + (size_t)q*WSZ + Wp);
        *(float4*)op = make_float4(acc[i][0], acc[i][1], acc[i][2], acc[i][3]);
    }
}

extern "C" void kernel_launch(void* const* d_in, const int* in_sizes, int n_in,
                              void* d_out, int out_size)
{
    const float* x  = (const float*)d_in[0];
    const float* Ws = (const float*)d_in[1];
    const float* Hs = (const float*)d_in[2];
    const float* Cs = (const float*)d_in[3];
    float* out = (float*)d_out;

    dim3 gA(64, NC, NB);        // (p*8+q, c, b) -> 12288 CTAs
    k_stage12<<<gA, 256>>>(x, Ws, Hs);

    dim3 gB(WSZ*WSZ/128, NWIN); // (32 n-tiles, 256 windows) -> 8192 CTAs
    k_stage3<<<gB, 256>>>(Cs, out);
}